// round 2
// baseline (speedup 1.0000x reference)
#include <cuda_runtime.h>
#include <math.h>

#define NN 20000
#define EE 320000
#define GG 16

// ---------------- scratch (static __device__, no allocations) ----------------
__device__ float g_s   [NN*64];     // node scalar features
__device__ float g_v   [NN*96];     // node vector features [n][32][3]
__device__ float g_s1  [NN*64];
__device__ float g_v1  [NN*96];
__device__ float g_scs [NN*96];
__device__ float g_scv [NN*96];     // [n][32][3]
__device__ float g_a   [NN*96*4];   // packed accumulator [n][96][{ms,mv0,mv1,mv2}]
__device__ float g_remb[EE*8];
__device__ float g_sh1 [EE*3];

// ---------------- constants ----------------
#define SC_S_SCALE  0.0625f                 // 1/sqrt(64*4)
#define SC_V_SCALE  0.08838834764831845f    // 1/sqrt(32*4)
#define S1_SCALE    0.125f                  // 1/sqrt(64)
#define V1_SCALE    0.17677669529663687f    // 1/sqrt(32)
#define R0_SCALE    0.35355339059327373f    // 1/sqrt(8)
#define RMID_SCALE  0.125f                  // 1/sqrt(64)
#define AGG         0.25f                   // 1/sqrt(16)
#define MSG2        0.57735026918962576f    // 1/sqrt(3)
#define O_SCALE     0.10206207261596575f    // 1/sqrt(96)
#define EN1S        0.125f                  // 1/sqrt(64)
#define EN2S        0.17677669529663687f    // 1/sqrt(32)

__device__ __forceinline__ float silu_f(float x){ return x / (1.f + __expf(-x)); }

// ---------------- embed: s = nodes @ W_embed / 2 ; v = 0 ----------------
__global__ void k_embed(const float* __restrict__ nodes, const float* __restrict__ Wemb)
{
    int idx = blockIdx.x*blockDim.x + threadIdx.x;
    if (idx < NN*64) {
        int n = idx >> 6, o = idx & 63;
        const float* nd = nodes + n*4;
        float a = nd[0]*__ldg(&Wemb[o])     + nd[1]*__ldg(&Wemb[64+o])
                + nd[2]*__ldg(&Wemb[128+o]) + nd[3]*__ldg(&Wemb[192+o]);
        g_s[idx] = 0.5f * a;
    }
    if (idx < NN*96) g_v[idx] = 0.f;
}

// ---------------- edge geometry: bessel embedding + sh1 ----------------
__global__ void k_geom(const float* __restrict__ dR)
{
    int e = blockIdx.x*blockDim.x + threadIdx.x;
    if (e >= EE) return;
    float x = dR[e*3], y = dR[e*3+1], z = dR[e*3+2];
    float r  = sqrtf(x*x + y*y + z*z);
    float rs = fmaxf(r, 1e-6f);
    float inv = 1.f / rs;
    g_sh1[e*3+0] = 1.7320508075688772f * x * inv;
    g_sh1[e*3+1] = 1.7320508075688772f * y * inv;
    g_sh1[e*3+2] = 1.7320508075688772f * z * inv;
    float env;
    if (r < 3.5f)      env = 1.f;
    else if (r > 4.f)  env = 0.f;
    else {
        float t = (r - 3.5f) * 2.f;
        env = 0.5f * (cosf(3.14159265358979323846f * t) + 1.f);
    }
    float pref = 0.70710678118654752f * inv * env;  // sqrt(2/4)/r_safe * env
    #pragma unroll
    for (int nb = 1; nb <= 8; nb++)
        g_remb[e*8 + nb - 1] = pref * sinf((float)nb * 0.78539816339744831f * rs);
}

// ---------------- zero packed accumulator ----------------
__global__ void k_zero()
{
    int idx = blockIdx.x*blockDim.x + threadIdx.x;
    if (idx < NN*96) ((float4*)g_a)[idx] = make_float4(0.f,0.f,0.f,0.f);
}

__global__ void k_zero_energy(float* __restrict__ out)
{
    if (threadIdx.x < GG) out[threadIdx.x] = 0.f;
}

// ---------------- node pre: sc_s, sc_v, s1, v1 (4 nodes / iter) ----------------
__global__ void __launch_bounds__(128) k_node_pre(
    const float* __restrict__ nodes,
    const float* __restrict__ Wscs, const float* __restrict__ Wscv,
    const float* __restrict__ W1s,  const float* __restrict__ W1v)
{
    extern __shared__ float sm[];
    float* Wsh = sm;              // 24576  (256 x 96), layout matches (i*4+e)*96+o
    float* xs  = sm + 24576;      // 4*256
    float* xv  = sm + 25600;      // 4*384
    float* ssh = sm + 27136;      // 4*64
    float* vsh = sm + 27392;      // 4*96
    float* ash = sm + 27776;      // 16
    const int tid = threadIdx.x;

    for (int i = tid; i < 6144; i += 128)
        ((float4*)Wsh)[i] = __ldg(((const float4*)Wscs) + i);

    for (int g = blockIdx.x; g < NN/4; g += gridDim.x) {
        int n0 = g * 4;
        __syncthreads();
        for (int i = tid; i < 256; i += 128) ssh[i] = g_s[n0*64 + i];
        for (int i = tid; i < 384; i += 128) vsh[i] = g_v[n0*96 + i];
        if (tid < 16) ash[tid] = nodes[n0*4 + tid];
        __syncthreads();
        for (int i = tid; i < 1024; i += 128) {
            int m = i >> 8, k = i & 255;
            xs[i] = ssh[m*64 + (k>>2)] * ash[m*4 + (k&3)];
        }
        for (int i = tid; i < 1536; i += 128) {
            int m = i / 384, k = i - m*384;
            int k2 = k / 3, c = k - 3*k2;
            xv[i] = vsh[m*96 + (k2>>2)*3 + c] * ash[m*4 + (k2&3)];
        }
        __syncthreads();
        if (tid < 96) {
            float a0=0.f,a1=0.f,a2=0.f,a3=0.f;
            const float *x0=xs, *x1=xs+256, *x2=xs+512, *x3=xs+768;
            #pragma unroll 4
            for (int k = 0; k < 256; k++) {
                float w = Wsh[k*96 + tid];
                a0 = fmaf(x0[k], w, a0); a1 = fmaf(x1[k], w, a1);
                a2 = fmaf(x2[k], w, a2); a3 = fmaf(x3[k], w, a3);
            }
            g_scs[(n0+0)*96+tid] = a0*SC_S_SCALE;
            g_scs[(n0+1)*96+tid] = a1*SC_S_SCALE;
            g_scs[(n0+2)*96+tid] = a2*SC_S_SCALE;
            g_scs[(n0+3)*96+tid] = a3*SC_S_SCALE;
        }
        #pragma unroll
        for (int p = 0; p < 2; p++) {
            int idx = tid + p*128;
            if (idx < 32) {                       // sc_v  (o = idx)
                int o = idx;
                float acc[4][3];
                #pragma unroll
                for (int m=0;m<4;m++){acc[m][0]=0.f;acc[m][1]=0.f;acc[m][2]=0.f;}
                for (int k2 = 0; k2 < 128; k2++) {
                    float w = __ldg(&Wscv[k2*32 + o]);
                    #pragma unroll
                    for (int m = 0; m < 4; m++) {
                        const float* xvm = xv + m*384 + k2*3;
                        acc[m][0] = fmaf(xvm[0], w, acc[m][0]);
                        acc[m][1] = fmaf(xvm[1], w, acc[m][1]);
                        acc[m][2] = fmaf(xvm[2], w, acc[m][2]);
                    }
                }
                #pragma unroll
                for (int m = 0; m < 4; m++)
                    #pragma unroll
                    for (int c = 0; c < 3; c++)
                        g_scv[(n0+m)*96 + o*3 + c] = acc[m][c]*SC_V_SCALE;
            } else if (idx < 96) {                // s1  (o = idx-32)
                int o = idx - 32;
                float a[4] = {0.f,0.f,0.f,0.f};
                for (int i = 0; i < 64; i++) {
                    float w = __ldg(&W1s[i*64 + o]);
                    #pragma unroll
                    for (int m = 0; m < 4; m++) a[m] = fmaf(ssh[m*64+i], w, a[m]);
                }
                #pragma unroll
                for (int m = 0; m < 4; m++) g_s1[(n0+m)*64 + o] = a[m]*S1_SCALE;
            } else if (idx < 192) {               // v1  (q = idx-96)
                int q = idx - 96, o = q & 31, c = q >> 5;
                float a[4] = {0.f,0.f,0.f,0.f};
                for (int i = 0; i < 32; i++) {
                    float w = __ldg(&W1v[i*32 + o]);
                    #pragma unroll
                    for (int m = 0; m < 4; m++) a[m] = fmaf(vsh[m*96 + i*3 + c], w, a[m]);
                }
                #pragma unroll
                for (int m = 0; m < 4; m++) g_v1[(n0+m)*96 + o*3 + c] = a[m]*V1_SCALE;
            }
        }
    }
}

// ---------------- fused edge kernel: radial MLP + message + v4 scatter ----------------
__global__ void __launch_bounds__(128,2) k_edge(
    const int* __restrict__ snd, const int* __restrict__ rcv,
    const float* __restrict__ R0, const float* __restrict__ R1,
    const float* __restrict__ R2)
{
    extern __shared__ float sm[];
    float* R0s = sm;               // 512
    float* R1s = sm + 512;         // 4096
    float* R2s = sm + 4608;        // 12288 (union: se @4608, ve @6656 after W phase)
    float* rem = sm + 16896;       // 256
    float* shs = sm + 17152;       // 96
    int*   idxs= (int*)(sm + 17248); // 64 ints
    float* H1  = sm + 17312;       // 2048
    float* H2  = sm + 19360;       // 2048
    float* Wm  = sm + 21408;       // 6144
    // total 27552 floats = 110208 B

    const int tid = threadIdx.x;
    const int e0  = blockIdx.x * 32;

    for (int i = tid; i < 128;  i += 128) ((float4*)R0s)[i] = __ldg(((const float4*)R0)+i);
    for (int i = tid; i < 1024; i += 128) ((float4*)R1s)[i] = __ldg(((const float4*)R1)+i);
    for (int i = tid; i < 3072; i += 128) ((float4*)R2s)[i] = __ldg(((const float4*)R2)+i);
    for (int i = tid; i < 64;   i += 128) ((float4*)rem)[i] = ((const float4*)(g_remb + e0*8))[i];
    for (int i = tid; i < 96;   i += 128) shs[i] = g_sh1[e0*3 + i];
    if (tid < 32) { idxs[tid] = snd[e0+tid]; idxs[32+tid] = rcv[e0+tid]; }
    __syncthreads();

    // ---- H1 = silu(remb @ R0 / sqrt(8)) ----
    for (int i = tid; i < 2048; i += 128) {
        int e = i >> 6, o = i & 63;
        const float* rp = rem + e*8;
        float a = 0.f;
        #pragma unroll
        for (int k = 0; k < 8; k++) a = fmaf(rp[k], R0s[k*64 + o], a);
        H1[i] = silu_f(a * R0_SCALE);
    }
    __syncthreads();

    const int te = tid >> 4;   // 0..7 : edge quad (edges 4*te..4*te+3)
    const int to = tid & 15;   // 0..15

    // ---- H2 = silu(H1 @ R1 / 8) : 4 edges x 4 outs / thread ----
    {
        const float* h0 = H1 + te*256;
        const int to4 = to*4;
        float4 acc0 = make_float4(0,0,0,0), acc1 = acc0, acc2 = acc0, acc3 = acc0;
        #pragma unroll 2
        for (int k = 0; k < 64; k += 4) {
            float4 hA = *(const float4*)(h0 + k);
            float4 hB = *(const float4*)(h0 + 64  + k);
            float4 hC = *(const float4*)(h0 + 128 + k);
            float4 hD = *(const float4*)(h0 + 192 + k);
            float4 r0v = *(const float4*)(R1s + (k  )*64 + to4);
            float4 r1v = *(const float4*)(R1s + (k+1)*64 + to4);
            float4 r2v = *(const float4*)(R1s + (k+2)*64 + to4);
            float4 r3v = *(const float4*)(R1s + (k+3)*64 + to4);
#define ACC4(ACC,H) \
    ACC.x = fmaf(H.x,r0v.x,fmaf(H.y,r1v.x,fmaf(H.z,r2v.x,fmaf(H.w,r3v.x,ACC.x)))); \
    ACC.y = fmaf(H.x,r0v.y,fmaf(H.y,r1v.y,fmaf(H.z,r2v.y,fmaf(H.w,r3v.y,ACC.y)))); \
    ACC.z = fmaf(H.x,r0v.z,fmaf(H.y,r1v.z,fmaf(H.z,r2v.z,fmaf(H.w,r3v.z,ACC.z)))); \
    ACC.w = fmaf(H.x,r0v.w,fmaf(H.y,r1v.w,fmaf(H.z,r2v.w,fmaf(H.w,r3v.w,ACC.w))));
            ACC4(acc0,hA) ACC4(acc1,hB) ACC4(acc2,hC) ACC4(acc3,hD)
#undef ACC4
        }
        *(float4*)(H2 + (te*4+0)*64 + to4) = make_float4(
            silu_f(acc0.x*RMID_SCALE), silu_f(acc0.y*RMID_SCALE),
            silu_f(acc0.z*RMID_SCALE), silu_f(acc0.w*RMID_SCALE));
        *(float4*)(H2 + (te*4+1)*64 + to4) = make_float4(
            silu_f(acc1.x*RMID_SCALE), silu_f(acc1.y*RMID_SCALE),
            silu_f(acc1.z*RMID_SCALE), silu_f(acc1.w*RMID_SCALE));
        *(float4*)(H2 + (te*4+2)*64 + to4) = make_float4(
            silu_f(acc2.x*RMID_SCALE), silu_f(acc2.y*RMID_SCALE),
            silu_f(acc2.z*RMID_SCALE), silu_f(acc2.w*RMID_SCALE));
        *(float4*)(H2 + (te*4+3)*64 + to4) = make_float4(
            silu_f(acc3.x*RMID_SCALE), silu_f(acc3.y*RMID_SCALE),
            silu_f(acc3.z*RMID_SCALE), silu_f(acc3.w*RMID_SCALE));
    }
    __syncthreads();

    // ---- W = H2 @ R2 / 8 : 4 edges x 12 outs / thread ----
    {
        const float* h0 = H2 + te*256;
        float acc[4][12];
        #pragma unroll
        for (int j = 0; j < 4; j++)
            #pragma unroll
            for (int q = 0; q < 12; q++) acc[j][q] = 0.f;
        for (int k = 0; k < 64; k++) {
            const float* rrow = R2s + k*192 + to*12;
            float4 ra = *(const float4*)(rrow);
            float4 rb = *(const float4*)(rrow + 4);
            float4 rc = *(const float4*)(rrow + 8);
            #pragma unroll
            for (int j = 0; j < 4; j++) {
                float h = h0[j*64 + k];
                acc[j][0]  = fmaf(h, ra.x, acc[j][0]);
                acc[j][1]  = fmaf(h, ra.y, acc[j][1]);
                acc[j][2]  = fmaf(h, ra.z, acc[j][2]);
                acc[j][3]  = fmaf(h, ra.w, acc[j][3]);
                acc[j][4]  = fmaf(h, rb.x, acc[j][4]);
                acc[j][5]  = fmaf(h, rb.y, acc[j][5]);
                acc[j][6]  = fmaf(h, rb.z, acc[j][6]);
                acc[j][7]  = fmaf(h, rb.w, acc[j][7]);
                acc[j][8]  = fmaf(h, rc.x, acc[j][8]);
                acc[j][9]  = fmaf(h, rc.y, acc[j][9]);
                acc[j][10] = fmaf(h, rc.z, acc[j][10]);
                acc[j][11] = fmaf(h, rc.w, acc[j][11]);
            }
        }
        #pragma unroll
        for (int j = 0; j < 4; j++)
            #pragma unroll
            for (int q = 0; q < 12; q++)
                Wm[(te*4+j)*192 + to*12 + q] = acc[j][q]*RMID_SCALE;
    }
    __syncthreads();

    // ---- stage gathered se / ve into smem (union over R2s region) ----
    float* seb = R2s;          // 2048
    float* veb = R2s + 2048;   // 3072
    for (int i = tid; i < 2048; i += 128) {
        int e = i >> 6, o = i & 63;
        seb[i] = __ldg(&g_s1[idxs[e]*64 + o]);
    }
    for (int i = tid; i < 3072; i += 128) {
        int e = i / 96, q = i - e*96;
        veb[i] = __ldg(&g_v1[idxs[e]*96 + q]);
    }
    __syncthreads();

    // ---- messages + packed v4 scatter ----
    for (int i = tid; i < 3072; i += 128) {
        int e = i / 96, o = i - e*96;
        const float* we = Wm + e*192;
        float sx = shs[e*3], sy = shs[e*3+1], sz = shs[e*3+2];
        float ms, m0, m1, m2;
        if (o < 64) {
            float sev = seb[e*64 + o];
            ms = we[o] * sev;
            float t = we[64+o] * sev;
            m0 = t*sx; m1 = t*sy; m2 = t*sz;
        } else {
            int oo = o - 64;
            const float* vp = veb + e*96 + oo*3;
            float w3 = we[128+oo], w4 = we[160+oo];
            ms = w4 * (vp[0]*sx + vp[1]*sy + vp[2]*sz) * MSG2;
            m0 = w3*vp[0]; m1 = w3*vp[1]; m2 = w3*vp[2];
        }
        float* addr = g_a + ((size_t)idxs[32+e]*96 + o)*4;
        asm volatile("red.global.add.v4.f32 [%0], {%1,%2,%3,%4};"
            :: "l"(addr), "f"(ms*AGG), "f"(m0*AGG), "f"(m1*AGG), "f"(m2*AGG)
            : "memory");
    }
}

// ---------------- node post: o_s, o_v, gate -> new s, v ----------------
__global__ void __launch_bounds__(128) k_node_post(
    const float* __restrict__ W2s, const float* __restrict__ W2v)
{
    extern __shared__ float sm[];
    float* W2ss = sm;          // 9216
    float* W2vs = sm + 9216;   // 3072
    float* asb  = sm + 12288;  // 384
    float* avb  = sm + 12672;  // 1152
    float* osh  = sm + 13824;  // 384
    // total 14208 floats = 56832 B
    const int tid = threadIdx.x;

    for (int i = tid; i < 9216; i += 128) W2ss[i] = __ldg(&W2s[i]);
    for (int i = tid; i < 3072; i += 128) W2vs[i] = __ldg(&W2v[i]);

    for (int g = blockIdx.x; g < NN/4; g += gridDim.x) {
        int n0 = g * 4;
        __syncthreads();
        for (int i = tid; i < 384; i += 128) {
            float4 p = ((const float4*)g_a)[(size_t)n0*96 + i];
            asb[i] = p.x;
            avb[i*3+0] = p.y; avb[i*3+1] = p.z; avb[i*3+2] = p.w;
        }
        __syncthreads();
        for (int t = tid; t < 384; t += 128) {
            int m = t / 96, o = t - m*96;
            const float* ap = asb + m*96;
            float acc = 0.f;
            #pragma unroll 4
            for (int i = 0; i < 96; i++) acc = fmaf(ap[i], W2ss[i*96 + o], acc);
            osh[t] = acc*O_SCALE + g_scs[(n0+m)*96 + o];
        }
        __syncthreads();
        for (int t = tid; t < 256; t += 128) {
            int m = t >> 6, o = t & 63;
            g_s[(n0+m)*64 + o] = silu_f(osh[m*96 + o]);
        }
        for (int t = tid; t < 384; t += 128) {
            int m = t / 96, q = t - m*96;
            int o = q / 3, c = q - 3*o;
            const float* ap = avb + m*288 + c;
            float acc = 0.f;
            #pragma unroll 4
            for (int i = 0; i < 96; i++) acc = fmaf(ap[i*3], W2vs[i*32 + o], acc);
            float val = acc*O_SCALE + g_scv[(n0+m)*96 + q];
            float gate = silu_f(osh[m*96 + 64 + o]);
            g_v[(n0+m)*96 + q] = val * gate;
        }
    }
}

// ---------------- readout: energy + mags ----------------
__global__ void __launch_bounds__(128) k_final(
    const float* __restrict__ nodes,
    const float* __restrict__ W_en1, const float* __restrict__ W_en2,
    const float* __restrict__ W_mag1, const float* __restrict__ W_mag2,
    const float* __restrict__ sc_occ, const float* __restrict__ sh_occ,
    const float* __restrict__ esc, const float* __restrict__ esh,
    float* __restrict__ out)
{
    __shared__ float ssh[256];
    const int tid = threadIdx.x;
    const int w = tid >> 5, lane = tid & 31;
    const int n = blockIdx.x*4 + w;

    for (int i = tid; i < 256; i += 128) ssh[i] = g_s[blockIdx.x*256 + i];
    __syncthreads();

    const float* sp = ssh + w*64;
    float he = 0.f, hm = 0.f;
    #pragma unroll 4
    for (int i = 0; i < 64; i++) {
        float sv = sp[i];
        he = fmaf(sv, __ldg(&W_en1[i*32 + lane]),  he);
        hm = fmaf(sv, __ldg(&W_mag1[i*32 + lane]), hm);
    }
    he *= EN1S; hm *= EN1S;
    float ev = he * __ldg(&W_en2[lane]);
    float m0 = hm * __ldg(&W_mag2[lane*2]);
    float m1 = hm * __ldg(&W_mag2[lane*2+1]);
    #pragma unroll
    for (int off = 16; off > 0; off >>= 1) {
        ev += __shfl_xor_sync(0xffffffffu, ev, off);
        m0 += __shfl_xor_sync(0xffffffffu, m0, off);
        m1 += __shfl_xor_sync(0xffffffffu, m1, off);
    }
    if (lane == 0) {
        float atomic = __ldg(esc) * (ev*EN2S) + __ldg(esh);
        atomicAdd(&out[n/1250], atomic);
        float o0 = nodes[n*4], o1 = nodes[n*4+1], o2 = nodes[n*4+2];
        float sA = o0*__ldg(&sc_occ[0]) + o1*__ldg(&sc_occ[2]) + o2*__ldg(&sc_occ[4]);
        float sB = o0*__ldg(&sc_occ[1]) + o1*__ldg(&sc_occ[3]) + o2*__ldg(&sc_occ[5]);
        float hA = o0*__ldg(&sh_occ[0]) + o1*__ldg(&sh_occ[2]) + o2*__ldg(&sh_occ[4]);
        float hB = o0*__ldg(&sh_occ[1]) + o1*__ldg(&sh_occ[3]) + o2*__ldg(&sh_occ[5]);
        out[GG + n*2]     = sA*(m0*EN2S) + hA;
        out[GG + n*2 + 1] = sB*(m1*EN2S) + hB;
    }
}

// ---------------- launch ----------------
extern "C" void kernel_launch(void* const* d_in, const int* in_sizes, int n_in,
                              void* d_out, int out_size)
{
    const float* nodes   = (const float*)d_in[0];
    const float* dR      = (const float*)d_in[1];
    const int*   snd     = (const int*)  d_in[2];
    const int*   rcv     = (const int*)  d_in[3];
    // d_in[4] = n_node (constant 1250 per group; hardcoded)
    const float* W_embed = (const float*)d_in[5];
    const float* W_sc_s  = (const float*)d_in[6];
    const float* W_sc_v  = (const float*)d_in[7];
    const float* W_l1_s  = (const float*)d_in[8];
    const float* W_l1_v  = (const float*)d_in[9];
    const float* Wr0     = (const float*)d_in[10];
    const float* Wr1     = (const float*)d_in[11];
    const float* Wr2     = (const float*)d_in[12];
    const float* W_l2_s  = (const float*)d_in[13];
    const float* W_l2_v  = (const float*)d_in[14];
    const float* W_en1   = (const float*)d_in[15];
    const float* W_en2   = (const float*)d_in[16];
    const float* W_mag1  = (const float*)d_in[17];
    const float* W_mag2  = (const float*)d_in[18];
    const float* sc_occ  = (const float*)d_in[19];
    const float* sh_occ  = (const float*)d_in[20];
    const float* esc     = (const float*)d_in[21];
    const float* esh     = (const float*)d_in[22];
    float* out = (float*)d_out;

    cudaFuncSetAttribute(k_edge,      cudaFuncAttributeMaxDynamicSharedMemorySize, 110208);
    cudaFuncSetAttribute(k_node_pre,  cudaFuncAttributeMaxDynamicSharedMemorySize, 111168);
    cudaFuncSetAttribute(k_node_post, cudaFuncAttributeMaxDynamicSharedMemorySize, 56832);

    k_zero_energy<<<1, 32>>>(out);
    k_embed<<<(NN*96 + 255)/256, 256>>>(nodes, W_embed);
    k_geom<<<(EE + 255)/256, 256>>>(dR);

    for (int l = 0; l < 2; l++) {
        k_zero<<<(NN*96 + 255)/256, 256>>>();
        k_node_pre<<<296, 128, 111168>>>(nodes,
            W_sc_s + l*24576, W_sc_v + l*4096,
            W_l1_s + l*4096,  W_l1_v + l*1024);
        k_edge<<<EE/32, 128, 110208>>>(snd, rcv,
            Wr0 + l*512, Wr1 + l*4096, Wr2 + l*12288);
        k_node_post<<<592, 128, 56832>>>(W_l2_s + l*9216, W_l2_v + l*3072);
    }

    k_final<<<NN/4, 128>>>(nodes, W_en1, W_en2, W_mag1, W_mag2,
                           sc_occ, sh_occ, esc, esh, out);
}

// round 3
// speedup vs baseline: 1.3082x; 1.3082x over previous
#include <cuda_runtime.h>
#include <math.h>

#define NN 20000
#define EE 320000
#define GG 16
#define NTILE (EE/32)

typedef unsigned long long ull;

// ---------------- scratch (static __device__, no allocations) ----------------
__device__ float g_s   [NN*64];
__device__ float g_v   [NN*96];
__device__ float g_s1  [NN*64];
__device__ float g_v1  [NN*96];
__device__ float g_scs [NN*96];
__device__ float g_scv [NN*96];
__device__ float g_a   [NN*96*4];   // packed accumulator [n][96][{ms,mv0,mv1,mv2}]
__device__ float g_remb[EE*8];
__device__ float g_sh1 [EE*3];

// ---------------- constants ----------------
#define SC_S_SCALE  0.0625f
#define SC_V_SCALE  0.08838834764831845f
#define S1_SCALE    0.125f
#define V1_SCALE    0.17677669529663687f
#define R0_SCALE    0.35355339059327373f
#define RMID_SCALE  0.125f
#define AGG         0.25f
#define MSG2        0.57735026918962576f
#define O_SCALE     0.10206207261596575f
#define EN1S        0.125f
#define EN2S        0.17677669529663687f

__device__ __forceinline__ float silu_f(float x){ return x / (1.f + __expf(-x)); }

__device__ __forceinline__ ull f2_fma(ull a, ull b, ull c){
    ull d; asm("fma.rn.f32x2 %0,%1,%2,%3;" : "=l"(d) : "l"(a), "l"(b), "l"(c));
    return d;
}
__device__ __forceinline__ ull f2_dup(float x){
    ull d; unsigned u = __float_as_uint(x);
    asm("mov.b64 %0,{%1,%1};" : "=l"(d) : "r"(u));
    return d;
}
__device__ __forceinline__ float2 f2_unpack(ull v){
    unsigned lo, hi;
    asm("mov.b64 {%0,%1},%2;" : "=r"(lo), "=r"(hi) : "l"(v));
    return make_float2(__uint_as_float(lo), __uint_as_float(hi));
}

// ---------------- embed: s = nodes @ W_embed / 2 ; v = 0 ; zero energy ----------------
__global__ void k_embed(const float* __restrict__ nodes, const float* __restrict__ Wemb,
                        float* __restrict__ out)
{
    int idx = blockIdx.x*blockDim.x + threadIdx.x;
    if (blockIdx.x == 0 && threadIdx.x < GG) out[threadIdx.x] = 0.f;
    if (idx < NN*64) {
        int n = idx >> 6, o = idx & 63;
        const float* nd = nodes + n*4;
        float a = nd[0]*__ldg(&Wemb[o])     + nd[1]*__ldg(&Wemb[64+o])
                + nd[2]*__ldg(&Wemb[128+o]) + nd[3]*__ldg(&Wemb[192+o]);
        g_s[idx] = 0.5f * a;
    }
    if (idx < NN*96) g_v[idx] = 0.f;
}

// ---------------- edge geometry ----------------
__global__ void k_geom(const float* __restrict__ dR)
{
    int e = blockIdx.x*blockDim.x + threadIdx.x;
    if (e >= EE) return;
    float x = dR[e*3], y = dR[e*3+1], z = dR[e*3+2];
    float r  = sqrtf(x*x + y*y + z*z);
    float rs = fmaxf(r, 1e-6f);
    float inv = 1.f / rs;
    g_sh1[e*3+0] = 1.7320508075688772f * x * inv;
    g_sh1[e*3+1] = 1.7320508075688772f * y * inv;
    g_sh1[e*3+2] = 1.7320508075688772f * z * inv;
    float env;
    if (r < 3.5f)      env = 1.f;
    else if (r > 4.f)  env = 0.f;
    else {
        float t = (r - 3.5f) * 2.f;
        env = 0.5f * (cosf(3.14159265358979323846f * t) + 1.f);
    }
    float pref = 0.70710678118654752f * inv * env;
    #pragma unroll
    for (int nb = 1; nb <= 8; nb++)
        g_remb[e*8 + nb - 1] = pref * sinf((float)nb * 0.78539816339744831f * rs);
}

// ---------------- node pre: sc_s, sc_v, s1, v1 + zero g_a ----------------
__global__ void __launch_bounds__(128) k_node_pre(
    const float* __restrict__ nodes,
    const float* __restrict__ Wscs, const float* __restrict__ Wscv,
    const float* __restrict__ W1s,  const float* __restrict__ W1v)
{
    extern __shared__ float sm[];
    float* Wsh = sm;              // 24576  (256 x 96)
    float* xs  = sm + 24576;      // 1024
    float* xv  = sm + 25600;      // 1536
    float* ssh = sm + 27136;      // 256
    float* vsh = sm + 27392;      // 384
    float* ash = sm + 27776;      // 16
    const int tid = threadIdx.x;

    for (int i = tid; i < 6144; i += 128)
        ((float4*)Wsh)[i] = __ldg(((const float4*)Wscs) + i);

    for (int g = blockIdx.x; g < NN/4; g += gridDim.x) {
        int n0 = g * 4;
        __syncthreads();
        for (int i = tid; i < 256; i += 128) ssh[i] = g_s[n0*64 + i];
        for (int i = tid; i < 384; i += 128) vsh[i] = g_v[n0*96 + i];
        if (tid < 16) ash[tid] = nodes[n0*4 + tid];
        // zero the packed accumulator for these 4 nodes
        for (int i = tid; i < 384; i += 128)
            ((float4*)g_a)[(size_t)n0*96 + i] = make_float4(0.f,0.f,0.f,0.f);
        __syncthreads();
        for (int i = tid; i < 1024; i += 128) {
            int m = i >> 8, k = i & 255;
            xs[i] = ssh[m*64 + (k>>2)] * ash[m*4 + (k&3)];
        }
        for (int i = tid; i < 1536; i += 128) {
            int m = i / 384, k = i - m*384;
            int k2 = k / 3, c = k - 3*k2;
            xv[i] = vsh[m*96 + (k2>>2)*3 + c] * ash[m*4 + (k2&3)];
        }
        __syncthreads();
        if (tid < 96) {
            // ---- sc_s : column o = tid ----
            {
                float a0=0.f,a1=0.f,a2=0.f,a3=0.f;
                const float *x0=xs, *x1=xs+256, *x2=xs+512, *x3=xs+768;
                #pragma unroll 4
                for (int k = 0; k < 256; k++) {
                    float w = Wsh[k*96 + tid];
                    a0 = fmaf(x0[k], w, a0); a1 = fmaf(x1[k], w, a1);
                    a2 = fmaf(x2[k], w, a2); a3 = fmaf(x3[k], w, a3);
                }
                g_scs[(n0+0)*96+tid] = a0*SC_S_SCALE;
                g_scs[(n0+1)*96+tid] = a1*SC_S_SCALE;
                g_scs[(n0+2)*96+tid] = a2*SC_S_SCALE;
                g_scs[(n0+3)*96+tid] = a3*SC_S_SCALE;
            }
            // ---- sc_v : (o,c) = (tid/3, tid%3) ----
            {
                int o = tid / 3, c = tid - 3*o;
                float a0=0.f,a1=0.f,a2=0.f,a3=0.f;
                #pragma unroll 4
                for (int k2 = 0; k2 < 128; k2++) {
                    float w = __ldg(&Wscv[k2*32 + o]);
                    a0 = fmaf(xv[        k2*3 + c], w, a0);
                    a1 = fmaf(xv[384  +  k2*3 + c], w, a1);
                    a2 = fmaf(xv[768  +  k2*3 + c], w, a2);
                    a3 = fmaf(xv[1152 +  k2*3 + c], w, a3);
                }
                g_scv[(n0+0)*96 + o*3 + c] = a0*SC_V_SCALE;
                g_scv[(n0+1)*96 + o*3 + c] = a1*SC_V_SCALE;
                g_scv[(n0+2)*96 + o*3 + c] = a2*SC_V_SCALE;
                g_scv[(n0+3)*96 + o*3 + c] = a3*SC_V_SCALE;
            }
        } else {
            int t = tid - 96;  // 0..31
            // ---- s1 : columns t and t+32 ----
            #pragma unroll
            for (int half = 0; half < 2; half++) {
                int o = t + half*32;
                float a0=0.f,a1=0.f,a2=0.f,a3=0.f;
                #pragma unroll 4
                for (int i = 0; i < 64; i++) {
                    float w = __ldg(&W1s[i*64 + o]);
                    a0 = fmaf(ssh[i],     w, a0);
                    a1 = fmaf(ssh[64+i],  w, a1);
                    a2 = fmaf(ssh[128+i], w, a2);
                    a3 = fmaf(ssh[192+i], w, a3);
                }
                g_s1[(n0+0)*64+o] = a0*S1_SCALE;
                g_s1[(n0+1)*64+o] = a1*S1_SCALE;
                g_s1[(n0+2)*64+o] = a2*S1_SCALE;
                g_s1[(n0+3)*64+o] = a3*S1_SCALE;
            }
            // ---- v1 : q = t, t+32, t+64 ----
            #pragma unroll
            for (int part = 0; part < 3; part++) {
                int q = t + part*32;
                int o = q & 31, c = q >> 5;
                float a0=0.f,a1=0.f,a2=0.f,a3=0.f;
                #pragma unroll 4
                for (int i = 0; i < 32; i++) {
                    float w = __ldg(&W1v[i*32 + o]);
                    a0 = fmaf(vsh[       i*3 + c], w, a0);
                    a1 = fmaf(vsh[ 96 +  i*3 + c], w, a1);
                    a2 = fmaf(vsh[192 +  i*3 + c], w, a2);
                    a3 = fmaf(vsh[288 +  i*3 + c], w, a3);
                }
                g_v1[(n0+0)*96 + o*3 + c] = a0*V1_SCALE;
                g_v1[(n0+1)*96 + o*3 + c] = a1*V1_SCALE;
                g_v1[(n0+2)*96 + o*3 + c] = a2*V1_SCALE;
                g_v1[(n0+3)*96 + o*3 + c] = a3*V1_SCALE;
            }
        }
    }
}

// ---------------- persistent fused edge kernel (f32x2 MLP) ----------------
__global__ void __launch_bounds__(128,2) k_edge(
    const int* __restrict__ snd, const int* __restrict__ rcv,
    const float* __restrict__ R0, const float* __restrict__ R1,
    const float* __restrict__ R2)
{
    extern __shared__ float sm[];
    float* R0s = sm;                 // 512
    float* R1s = sm + 512;           // 4096
    float* R2s = sm + 4608;          // 12288
    float* rem = sm + 16896;         // 256
    float* shs = sm + 17152;         // 96
    int*   idxs= (int*)(sm + 17248); // 64 ints
    float* H1  = sm + 17312;         // 2048
    float* H2  = sm + 19360;         // 2048
    float* Wm  = sm + 21408;         // 6144
    // total 27552 floats = 110208 B

    const int tid = threadIdx.x;
    const int te  = tid >> 4;        // 0..7
    const int to  = tid & 15;        // 0..15
    const int to4 = to * 4;

    // weights once per block (persistent)
    for (int i = tid; i < 128;  i += 128) ((float4*)R0s)[i] = __ldg(((const float4*)R0)+i);
    for (int i = tid; i < 1024; i += 128) ((float4*)R1s)[i] = __ldg(((const float4*)R1)+i);
    for (int i = tid; i < 3072; i += 128) ((float4*)R2s)[i] = __ldg(((const float4*)R2)+i);

    for (int tile = blockIdx.x; tile < NTILE; tile += gridDim.x) {
        const int e0 = tile * 32;
        __syncthreads();   // protects rem/shs/idxs/H*/Wm reuse from previous tile
        for (int i = tid; i < 64;   i += 128) ((float4*)rem)[i] = ((const float4*)(g_remb + e0*8))[i];
        for (int i = tid; i < 96;   i += 128) shs[i] = g_sh1[e0*3 + i];
        if (tid < 32) { idxs[tid] = snd[e0+tid]; idxs[32+tid] = rcv[e0+tid]; }
        __syncthreads();

        // ---- H1 = silu(remb @ R0 / sqrt(8)) ----
        for (int i = tid; i < 2048; i += 128) {
            int e = i >> 6, o = i & 63;
            const float* rp = rem + e*8;
            float a = 0.f;
            #pragma unroll
            for (int k = 0; k < 8; k++) a = fmaf(rp[k], R0s[k*64 + o], a);
            H1[i] = silu_f(a * R0_SCALE);
        }
        __syncthreads();

        // ---- H2 = silu(H1 @ R1 / 8) : 4 edges x 4 outs, packed f32x2 ----
        {
            const float* h0 = H1 + te*256;
            ull acc[4][2];
            #pragma unroll
            for (int e = 0; e < 4; e++) { acc[e][0] = 0ull; acc[e][1] = 0ull; }
            #pragma unroll 2
            for (int k = 0; k < 64; k += 4) {
                float h[4][4];
                #pragma unroll
                for (int e = 0; e < 4; e++)
                    *(float4*)h[e] = *(const float4*)(h0 + e*64 + k);
                #pragma unroll
                for (int kk = 0; kk < 4; kk++) {
                    ulonglong2 w = *(const ulonglong2*)(R1s + (k+kk)*64 + to4);
                    #pragma unroll
                    for (int e = 0; e < 4; e++) {
                        ull hd = f2_dup(h[e][kk]);
                        acc[e][0] = f2_fma(hd, w.x, acc[e][0]);
                        acc[e][1] = f2_fma(hd, w.y, acc[e][1]);
                    }
                }
            }
            #pragma unroll
            for (int e = 0; e < 4; e++) {
                float2 p0 = f2_unpack(acc[e][0]);
                float2 p1 = f2_unpack(acc[e][1]);
                *(float4*)(H2 + (te*4+e)*64 + to4) = make_float4(
                    silu_f(p0.x*RMID_SCALE), silu_f(p0.y*RMID_SCALE),
                    silu_f(p1.x*RMID_SCALE), silu_f(p1.y*RMID_SCALE));
            }
        }
        __syncthreads();

        // ---- W = H2 @ R2 / 8 : 4 edges x 12 outs, packed f32x2 ----
        {
            const float* h0 = H2 + te*256;
            ull acc[4][6];
            #pragma unroll
            for (int e = 0; e < 4; e++)
                #pragma unroll
                for (int p = 0; p < 6; p++) acc[e][p] = 0ull;
            #pragma unroll 2
            for (int k = 0; k < 64; k += 4) {
                float h[4][4];
                #pragma unroll
                for (int e = 0; e < 4; e++)
                    *(float4*)h[e] = *(const float4*)(h0 + e*64 + k);
                #pragma unroll
                for (int kk = 0; kk < 4; kk++) {
                    const float* rrow = R2s + (k+kk)*192 + to*12;
                    ulonglong2 wA = *(const ulonglong2*)(rrow);
                    ulonglong2 wB = *(const ulonglong2*)(rrow + 4);
                    ulonglong2 wC = *(const ulonglong2*)(rrow + 8);
                    #pragma unroll
                    for (int e = 0; e < 4; e++) {
                        ull hd = f2_dup(h[e][kk]);
                        acc[e][0] = f2_fma(hd, wA.x, acc[e][0]);
                        acc[e][1] = f2_fma(hd, wA.y, acc[e][1]);
                        acc[e][2] = f2_fma(hd, wB.x, acc[e][2]);
                        acc[e][3] = f2_fma(hd, wB.y, acc[e][3]);
                        acc[e][4] = f2_fma(hd, wC.x, acc[e][4]);
                        acc[e][5] = f2_fma(hd, wC.y, acc[e][5]);
                    }
                }
            }
            #pragma unroll
            for (int e = 0; e < 4; e++) {
                float* wout = Wm + (te*4+e)*192 + to*12;
                #pragma unroll
                for (int p = 0; p < 6; p++) {
                    float2 q = f2_unpack(acc[e][p]);
                    wout[p*2]   = q.x*RMID_SCALE;
                    wout[p*2+1] = q.y*RMID_SCALE;
                }
            }
        }
        __syncthreads();

        // ---- messages (direct gather from L2) + packed v4 scatter ----
        #pragma unroll 6
        for (int j = 0; j < 24; j++) {
            int i = tid + j*128;
            int e = i / 96, o = i - e*96;
            const float* we = Wm + e*192;
            float sx = shs[e*3], sy = shs[e*3+1], sz = shs[e*3+2];
            float ms, m0, m1, m2;
            if (o < 64) {
                float sev = __ldg(&g_s1[idxs[e]*64 + o]);
                ms = we[o] * sev;
                float t = we[64+o] * sev;
                m0 = t*sx; m1 = t*sy; m2 = t*sz;
            } else {
                int oo = o - 64;
                const float* vp = &g_v1[idxs[e]*96 + oo*3];
                float v0 = __ldg(vp), v1 = __ldg(vp+1), v2 = __ldg(vp+2);
                float w3 = we[128+oo], w4 = we[160+oo];
                ms = w4 * (v0*sx + v1*sy + v2*sz) * MSG2;
                m0 = w3*v0; m1 = w3*v1; m2 = w3*v2;
            }
            float* addr = g_a + ((size_t)idxs[32+e]*96 + o)*4;
            asm volatile("red.global.add.v4.f32 [%0], {%1,%2,%3,%4};"
                :: "l"(addr), "f"(ms*AGG), "f"(m0*AGG), "f"(m1*AGG), "f"(m2*AGG)
                : "memory");
        }
    }
}

// ---------------- node post ----------------
__global__ void __launch_bounds__(128) k_node_post(
    const float* __restrict__ W2s, const float* __restrict__ W2v)
{
    extern __shared__ float sm[];
    float* W2ss = sm;          // 9216
    float* W2vs = sm + 9216;   // 3072
    float* asb  = sm + 12288;  // 384
    float* avb  = sm + 12672;  // 1152
    float* osh  = sm + 13824;  // 384
    const int tid = threadIdx.x;

    for (int i = tid; i < 9216; i += 128) W2ss[i] = __ldg(&W2s[i]);
    for (int i = tid; i < 3072; i += 128) W2vs[i] = __ldg(&W2v[i]);

    for (int g = blockIdx.x; g < NN/4; g += gridDim.x) {
        int n0 = g * 4;
        __syncthreads();
        for (int i = tid; i < 384; i += 128) {
            float4 p = ((const float4*)g_a)[(size_t)n0*96 + i];
            asb[i] = p.x;
            avb[i*3+0] = p.y; avb[i*3+1] = p.z; avb[i*3+2] = p.w;
        }
        __syncthreads();
        for (int t = tid; t < 384; t += 128) {
            int m = t / 96, o = t - m*96;
            const float* ap = asb + m*96;
            float acc = 0.f;
            #pragma unroll 4
            for (int i = 0; i < 96; i++) acc = fmaf(ap[i], W2ss[i*96 + o], acc);
            osh[t] = acc*O_SCALE + g_scs[(n0+m)*96 + o];
        }
        __syncthreads();
        for (int t = tid; t < 256; t += 128) {
            int m = t >> 6, o = t & 63;
            g_s[(n0+m)*64 + o] = silu_f(osh[m*96 + o]);
        }
        for (int t = tid; t < 384; t += 128) {
            int m = t / 96, q = t - m*96;
            int o = q / 3, c = q - 3*o;
            const float* ap = avb + m*288 + c;
            float acc = 0.f;
            #pragma unroll 4
            for (int i = 0; i < 96; i++) acc = fmaf(ap[i*3], W2vs[i*32 + o], acc);
            float val = acc*O_SCALE + g_scv[(n0+m)*96 + q];
            float gate = silu_f(osh[m*96 + 64 + o]);
            g_v[(n0+m)*96 + q] = val * gate;
        }
    }
}

// ---------------- readout ----------------
__global__ void __launch_bounds__(128) k_final(
    const float* __restrict__ nodes,
    const float* __restrict__ W_en1, const float* __restrict__ W_en2,
    const float* __restrict__ W_mag1, const float* __restrict__ W_mag2,
    const float* __restrict__ sc_occ, const float* __restrict__ sh_occ,
    const float* __restrict__ esc, const float* __restrict__ esh,
    float* __restrict__ out)
{
    __shared__ float ssh[256];
    const int tid = threadIdx.x;
    const int w = tid >> 5, lane = tid & 31;
    const int n = blockIdx.x*4 + w;

    for (int i = tid; i < 256; i += 128) ssh[i] = g_s[blockIdx.x*256 + i];
    __syncthreads();

    const float* sp = ssh + w*64;
    float he = 0.f, hm = 0.f;
    #pragma unroll 4
    for (int i = 0; i < 64; i++) {
        float sv = sp[i];
        he = fmaf(sv, __ldg(&W_en1[i*32 + lane]),  he);
        hm = fmaf(sv, __ldg(&W_mag1[i*32 + lane]), hm);
    }
    he *= EN1S; hm *= EN1S;
    float ev = he * __ldg(&W_en2[lane]);
    float m0 = hm * __ldg(&W_mag2[lane*2]);
    float m1 = hm * __ldg(&W_mag2[lane*2+1]);
    #pragma unroll
    for (int off = 16; off > 0; off >>= 1) {
        ev += __shfl_xor_sync(0xffffffffu, ev, off);
        m0 += __shfl_xor_sync(0xffffffffu, m0, off);
        m1 += __shfl_xor_sync(0xffffffffu, m1, off);
    }
    if (lane == 0) {
        float atomic = __ldg(esc) * (ev*EN2S) + __ldg(esh);
        atomicAdd(&out[n/1250], atomic);
        float o0 = nodes[n*4], o1 = nodes[n*4+1], o2 = nodes[n*4+2];
        float sA = o0*__ldg(&sc_occ[0]) + o1*__ldg(&sc_occ[2]) + o2*__ldg(&sc_occ[4]);
        float sB = o0*__ldg(&sc_occ[1]) + o1*__ldg(&sc_occ[3]) + o2*__ldg(&sc_occ[5]);
        float hA = o0*__ldg(&sh_occ[0]) + o1*__ldg(&sh_occ[2]) + o2*__ldg(&sh_occ[4]);
        float hB = o0*__ldg(&sh_occ[1]) + o1*__ldg(&sh_occ[3]) + o2*__ldg(&sh_occ[5]);
        out[GG + n*2]     = sA*(m0*EN2S) + hA;
        out[GG + n*2 + 1] = sB*(m1*EN2S) + hB;
    }
}

// ---------------- launch ----------------
extern "C" void kernel_launch(void* const* d_in, const int* in_sizes, int n_in,
                              void* d_out, int out_size)
{
    const float* nodes   = (const float*)d_in[0];
    const float* dR      = (const float*)d_in[1];
    const int*   snd     = (const int*)  d_in[2];
    const int*   rcv     = (const int*)  d_in[3];
    const float* W_embed = (const float*)d_in[5];
    const float* W_sc_s  = (const float*)d_in[6];
    const float* W_sc_v  = (const float*)d_in[7];
    const float* W_l1_s  = (const float*)d_in[8];
    const float* W_l1_v  = (const float*)d_in[9];
    const float* Wr0     = (const float*)d_in[10];
    const float* Wr1     = (const float*)d_in[11];
    const float* Wr2     = (const float*)d_in[12];
    const float* W_l2_s  = (const float*)d_in[13];
    const float* W_l2_v  = (const float*)d_in[14];
    const float* W_en1   = (const float*)d_in[15];
    const float* W_en2   = (const float*)d_in[16];
    const float* W_mag1  = (const float*)d_in[17];
    const float* W_mag2  = (const float*)d_in[18];
    const float* sc_occ  = (const float*)d_in[19];
    const float* sh_occ  = (const float*)d_in[20];
    const float* esc     = (const float*)d_in[21];
    const float* esh     = (const float*)d_in[22];
    float* out = (float*)d_out;

    cudaFuncSetAttribute(k_edge,      cudaFuncAttributeMaxDynamicSharedMemorySize, 110208);
    cudaFuncSetAttribute(k_node_pre,  cudaFuncAttributeMaxDynamicSharedMemorySize, 111168);
    cudaFuncSetAttribute(k_node_post, cudaFuncAttributeMaxDynamicSharedMemorySize, 56832);

    k_embed<<<(NN*96 + 255)/256, 256>>>(nodes, W_embed, out);
    k_geom<<<(EE + 255)/256, 256>>>(dR);

    for (int l = 0; l < 2; l++) {
        k_node_pre<<<296, 128, 111168>>>(nodes,
            W_sc_s + l*24576, W_sc_v + l*4096,
            W_l1_s + l*4096,  W_l1_v + l*1024);
        k_edge<<<296, 128, 110208>>>(snd, rcv,
            Wr0 + l*512, Wr1 + l*4096, Wr2 + l*12288);
        k_node_post<<<592, 128, 56832>>>(W_l2_s + l*9216, W_l2_v + l*3072);
    }

    k_final<<<NN/4, 128>>>(nodes, W_en1, W_en2, W_mag1, W_mag2,
                           sc_occ, sh_occ, esc, esh, out);
}